// round 16
// baseline (speedup 1.0000x reference)
#include <cuda_runtime.h>
#include <cuda_bf16.h>
#include <math.h>
#include <stdint.h>

#define NMAX   (1 << 19)
#define RMAX   8192
#define TBL    (1 << 19)
#define TMASK  (TBL - 1)

// ---------------- global scratch ----------------
__device__ float4   g_samp[NMAX];          // {r,g,b,s}
__device__ float    g_raypart[RMAX * 64];  // SH(dir) @ hw0[0:16,:]  (fp32 exact)
__device__ int      g_raystart[RMAX + 1];  // per-ray sample range bounds

// vectorized weight layouts: entry index = (ni*KS + ks)*32 + lane
__device__ uint2 g_Wv0 [8 * 2 * 32];       // X1: K=32,N=64, nosplit
__device__ uint2 g_Wv1 [2 * 4 * 32];       // H2: K=64,N=16, nosplit
__device__ uint2 g_Wve [8 * 1 * 32];       // X2: K=16,N=64, nosplit
__device__ uint4 g_Wvh1[8 * 4 * 32];       // X3: K=64,N=64, split {bh0,bh1,bl0,bl1}
__device__ uint4 g_Wvh2[1 * 4 * 32];       // X4: K=64,N=8,  split

struct ResTable { float r[16]; };

__device__ __forceinline__ unsigned packbf(float lo, float hi) {
    unsigned r;
    asm("cvt.rn.bf16x2.f32 %0, %1, %2;" : "=r"(r) : "f"(hi), "f"(lo));
    return r;
}
__device__ __forceinline__ float bfround(float v) {
    return __bfloat162float(__float2bfloat16_rn(v));
}

// ---------------------------------------------------------------------------
// prep: build vectorized bf16 weight layouts (hi/lo split for head l1,l2)
// ---------------------------------------------------------------------------
__global__ void prep_kernel(const float* __restrict__ w0, const float* __restrict__ w1,
                            const float* __restrict__ hw0, const float* __restrict__ hw1,
                            const float* __restrict__ hw2)
{
    int i = blockIdx.x * 256 + threadIdx.x;   // 0..1023
    int lane = i & 31, c = lane & 3, g = lane >> 2;

    // X3: hw1 (64x64), split, 1024 entries
    {
        int ni = i >> 7, ks = (i >> 5) & 3;
        int n = ni * 8 + g;
        int kp0 = ks * 8 + c, kp1 = kp0 + 4;
        float v00 = hw1[(2 * kp0) * 64 + n],     v01 = hw1[(2 * kp0 + 1) * 64 + n];
        float v10 = hw1[(2 * kp1) * 64 + n],     v11 = hw1[(2 * kp1 + 1) * 64 + n];
        float h00 = bfround(v00), h01 = bfround(v01);
        float h10 = bfround(v10), h11 = bfround(v11);
        g_Wvh1[i] = make_uint4(packbf(h00, h01), packbf(h10, h11),
                               packbf(v00 - h00, v01 - h01), packbf(v10 - h10, v11 - h11));
    }
    // X1: w0 (32x64), nosplit, 512 entries
    if (i < 512) {
        int ni = i >> 6, ks = (i >> 5) & 1;
        int n = ni * 8 + g;
        int kp0 = ks * 8 + c, kp1 = kp0 + 4;
        g_Wv0[i] = make_uint2(packbf(w0[(2 * kp0) * 64 + n], w0[(2 * kp0 + 1) * 64 + n]),
                              packbf(w0[(2 * kp1) * 64 + n], w0[(2 * kp1 + 1) * 64 + n]));
    }
    // H2: w1 (64x16), nosplit, 256 entries
    if (i < 256) {
        int ni = i >> 7, ks = (i >> 5) & 3;
        int n = ni * 8 + g;
        int kp0 = ks * 8 + c, kp1 = kp0 + 4;
        g_Wv1[i] = make_uint2(packbf(w1[(2 * kp0) * 16 + n], w1[(2 * kp0 + 1) * 16 + n]),
                              packbf(w1[(2 * kp1) * 16 + n], w1[(2 * kp1 + 1) * 16 + n]));
    }
    // X2: hw0 emb rows 16..30 (k-logical 0..14, pad 15), nosplit, 256 entries
    if (i < 256) {
        int ni = i >> 5;
        int n = ni * 8 + g;
        int kp0 = c, kp1 = c + 4;
        float e00 = (2 * kp0     < 15) ? hw0[(16 + 2 * kp0)     * 64 + n] : 0.f;
        float e01 = (2 * kp0 + 1 < 15) ? hw0[(16 + 2 * kp0 + 1) * 64 + n] : 0.f;
        float e10 = (2 * kp1     < 15) ? hw0[(16 + 2 * kp1)     * 64 + n] : 0.f;
        float e11 = (2 * kp1 + 1 < 15) ? hw0[(16 + 2 * kp1 + 1) * 64 + n] : 0.f;
        g_Wve[i] = make_uint2(packbf(e00, e01), packbf(e10, e11));
    }
    // X4: hw2 (64x3 pad 8), split, 128 entries
    if (i < 128) {
        int ks = i >> 5;
        int kp0 = ks * 8 + c, kp1 = kp0 + 4;
        float v00 = (g < 3) ? hw2[(2 * kp0) * 3 + g]     : 0.f;
        float v01 = (g < 3) ? hw2[(2 * kp0 + 1) * 3 + g] : 0.f;
        float v10 = (g < 3) ? hw2[(2 * kp1) * 3 + g]     : 0.f;
        float v11 = (g < 3) ? hw2[(2 * kp1 + 1) * 3 + g] : 0.f;
        float h00 = bfround(v00), h01 = bfround(v01);
        float h10 = bfround(v10), h11 = bfround(v11);
        g_Wvh2[i] = make_uint4(packbf(h00, h01), packbf(h10, h11),
                               packbf(v00 - h00, v01 - h01), packbf(v10 - h10, v11 - h11));
    }
}

// ---------------------------------------------------------------------------
// per-ray SH @ hw0[0:16,:]  (fp32 exact)
// ---------------------------------------------------------------------------
__global__ void raypart_kernel(const float* __restrict__ rd,
                               const float* __restrict__ hw0, int R)
{
    int idx = blockIdx.x * 256 + threadIdx.x;
    if (idx >= R * 64) return;
    int r = idx >> 6, n = idx & 63;
    float x = rd[3 * r + 0], y = rd[3 * r + 1], z = rd[3 * r + 2];
    float x2 = x * x, y2 = y * y, z2 = z * z;
    float xy = x * y, yz = y * z, xz = x * z;
    float sh[16];
    sh[0]  = 0.28209479177387814f;
    sh[1]  = -0.48860251190291987f * y;
    sh[2]  =  0.48860251190291987f * z;
    sh[3]  = -0.48860251190291987f * x;
    sh[4]  =  1.0925484305920792f * xy;
    sh[5]  = -1.0925484305920792f * yz;
    sh[6]  =  0.94617469575756f * z2 - 0.31539156525252005f;
    sh[7]  = -1.0925484305920792f * xz;
    sh[8]  =  0.5462742152960396f * (x2 - y2);
    sh[9]  = -0.5900435899266435f * y * (3.f * x2 - y2);
    sh[10] =  2.890611442640554f * xy * z;
    sh[11] = -0.4570457994644658f * y * (4.f * z2 - x2 - y2);
    sh[12] =  0.3731763325901154f * z * (2.f * z2 - 3.f * x2 - 3.f * y2);
    sh[13] = -0.4570457994644658f * x * (4.f * z2 - x2 - y2);
    sh[14] =  1.445305721320277f * z * (x2 - y2);
    sh[15] = -0.5900435899266435f * x * (x2 - 3.f * y2);
    float acc = 0.f;
#pragma unroll
    for (int k = 0; k < 16; k++) acc = fmaf(sh[k], hw0[k * 64 + n], acc);
    g_raypart[r * 64 + n] = acc;
}

// ---------------------------------------------------------------------------
// ray bounds: g_raystart[r] = first sample index of ray r (ridx sorted).
// Empty rays get start == end. Fully parallel; replaces accum binary search.
// ---------------------------------------------------------------------------
__global__ void raybounds_kernel(const int* __restrict__ ridx, int N, int R)
{
    int i = blockIdx.x * 256 + threadIdx.x;
    if (i >= N) return;
    int cur = ridx[i];
    int prev = (i == 0) ? -1 : ridx[i - 1];
    for (int r = prev + 1; r <= cur; r++) g_raystart[r] = i;
    if (i == N - 1) {
        for (int r = cur + 1; r <= R; r++) g_raystart[r] = N;
    }
}

// ---------------------------------------------------------------------------
// mma + fragment helpers (identical numerics to R15)
// ---------------------------------------------------------------------------
__device__ __forceinline__ void mma16(float c[4], unsigned a0, unsigned a1,
                                      unsigned a2, unsigned a3,
                                      unsigned b0, unsigned b1)
{
    asm volatile(
        "mma.sync.aligned.m16n8k16.row.col.f32.bf16.bf16.f32 "
        "{%0,%1,%2,%3}, {%4,%5,%6,%7}, {%8,%9}, {%0,%1,%2,%3};"
        : "+f"(c[0]), "+f"(c[1]), "+f"(c[2]), "+f"(c[3])
        : "r"(a0), "r"(a1), "r"(a2), "r"(a3), "r"(b0), "r"(b1));
}

template <int KS, int SIN>
__device__ __forceinline__ void load_afrag(const unsigned* sIn, int lane,
                                           unsigned a[2][4][4])
{
    const int g = lane >> 2, c = lane & 3;
#pragma unroll
    for (int mi = 0; mi < 2; mi++) {
        const int rA = mi * 16 + g;
#pragma unroll
        for (int ks = 0; ks < KS; ks++) {
            a[mi][ks][0] = sIn[(rA    ) * SIN + ks * 8 + c];
            a[mi][ks][1] = sIn[(rA + 8) * SIN + ks * 8 + c];
            a[mi][ks][2] = sIn[(rA    ) * SIN + ks * 8 + c + 4];
            a[mi][ks][3] = sIn[(rA + 8) * SIN + ks * 8 + c + 4];
        }
    }
}

// OUTMODE: 0 = register frag (hi only), 1 = register frag hi+lo, 2 = smem f32
template <int KS_IN, int NOUT, bool SPLIT, bool RELU, bool RPINIT, int OUTMODE, int SOUT>
__device__ __forceinline__ void gemm(
    const unsigned aHi[2][4][4], const unsigned aLo[2][4][4],
    const uint2* __restrict__ Wv2, const uint4* __restrict__ Wv4,
    const float* __restrict__ rayPart, const int* sRid,
    int lane,
    unsigned oHi[2][4][4], unsigned oLo[2][4][4], float* outF)
{
    const int g = lane >> 2, c = lane & 3;
    int ridA[2], ridB[2];
    if (RPINIT) {
#pragma unroll
        for (int mi = 0; mi < 2; mi++) {
            ridA[mi] = sRid[mi * 16 + g];
            ridB[mi] = sRid[mi * 16 + g + 8];
        }
    }

#pragma unroll
    for (int ni = 0; ni < NOUT / 8; ni++) {
        float acc[2][4];
#pragma unroll
        for (int mi = 0; mi < 2; mi++) {
            if (RPINIT) {
                float2 pa = __ldg((const float2*)(rayPart + ridA[mi] * 64 + ni * 8 + 2 * c));
                float2 pb = __ldg((const float2*)(rayPart + ridB[mi] * 64 + ni * 8 + 2 * c));
                acc[mi][0] = pa.x; acc[mi][1] = pa.y; acc[mi][2] = pb.x; acc[mi][3] = pb.y;
            } else {
                acc[mi][0] = acc[mi][1] = acc[mi][2] = acc[mi][3] = 0.f;
            }
        }
#pragma unroll
        for (int ks = 0; ks < KS_IN; ks++) {
            if (SPLIT) {
                uint4 wv = __ldg(Wv4 + ((ni * KS_IN + ks) << 5) + lane);
#pragma unroll
                for (int mi = 0; mi < 2; mi++) {
                    mma16(acc[mi], aHi[mi][ks][0], aHi[mi][ks][1],
                                   aHi[mi][ks][2], aHi[mi][ks][3], wv.x, wv.y);
                    mma16(acc[mi], aLo[mi][ks][0], aLo[mi][ks][1],
                                   aLo[mi][ks][2], aLo[mi][ks][3], wv.x, wv.y);
                    mma16(acc[mi], aHi[mi][ks][0], aHi[mi][ks][1],
                                   aHi[mi][ks][2], aHi[mi][ks][3], wv.z, wv.w);
                }
            } else {
                uint2 wv = __ldg(Wv2 + ((ni * KS_IN + ks) << 5) + lane);
#pragma unroll
                for (int mi = 0; mi < 2; mi++) {
                    mma16(acc[mi], aHi[mi][ks][0], aHi[mi][ks][1],
                                   aHi[mi][ks][2], aHi[mi][ks][3], wv.x, wv.y);
                }
            }
        }
#pragma unroll
        for (int mi = 0; mi < 2; mi++) {
            const int rA = mi * 16 + g;
            float v0 = acc[mi][0], v1 = acc[mi][1], v2 = acc[mi][2], v3 = acc[mi][3];
            if (RELU) {
                v0 = fmaxf(v0, 0.f); v1 = fmaxf(v1, 0.f);
                v2 = fmaxf(v2, 0.f); v3 = fmaxf(v3, 0.f);
            }
            if (OUTMODE == 2) {
                outF[(rA    ) * SOUT + ni * 8 + 2 * c    ] = v0;
                outF[(rA    ) * SOUT + ni * 8 + 2 * c + 1] = v1;
                outF[(rA + 8) * SOUT + ni * 8 + 2 * c    ] = v2;
                outF[(rA + 8) * SOUT + ni * 8 + 2 * c + 1] = v3;
            } else {
                const int ks_o = ni >> 1, sl = (ni & 1) * 2;
                oHi[mi][ks_o][sl    ] = packbf(v0, v1);
                oHi[mi][ks_o][sl + 1] = packbf(v2, v3);
                if (OUTMODE == 1) {
                    float h0 = bfround(v0), h1 = bfround(v1);
                    float h2 = bfround(v2), h3 = bfround(v3);
                    oLo[mi][ks_o][sl    ] = packbf(v0 - h0, v1 - h1);
                    oLo[mi][ks_o][sl + 1] = packbf(v2 - h2, v3 - h3);
                }
            }
        }
    }
}

// ---------------------------------------------------------------------------
// FUSED kernel: hash encode (1 thread/sample, 16 levels) -> register-resident
// MLP chain. 128 samples / block, 4 independent warps (only __syncwarp).
// per-warp slab (words):
//   WP_A   = 0     ENC s17 (544) / X4 f32 s9 (288, aliases; ENC dead after X1)
//   WP_C   = 544   H2 f32 s17 (544)
//   WP_EMB = 1088  s9 (288)
//   WP_RID = 1376  int x32
// dts and sigma-logit stay in the owning thread's registers (lane == row).
// ---------------------------------------------------------------------------
#define WP_A     0
#define WP_C     544
#define WP_EMB   1088
#define WP_RID   1376
#define WP_WORDS 1408
#define SMEM_U32 (4 * WP_WORDS)   // 5632 words = 22528 bytes

__global__ __launch_bounds__(128)
void fused_kernel(
    const float* __restrict__ ts, const float* __restrict__ te,
    const float* __restrict__ ro, const float* __restrict__ rd,
    const int*   __restrict__ ridx,
    const float* __restrict__ tables,
    const float* __restrict__ aabb,
    ResTable res, int N)
{
    extern __shared__ unsigned smu[];

    const int lane = threadIdx.x & 31;
    const int w = threadIdx.x >> 5;
    unsigned* wp = smu + w * WP_WORDS;
    float*    wpf = (float*)wp;
    int*      wpi = (int*)wp;
    const int base = blockIdx.x * 128 + w * 32;

    // ---------------- stage 0: hash encode own sample -> smem enc row -------
    const int gi0 = base + lane;
    const int iS = (gi0 < N) ? gi0 : (N - 1);   // clamp; extra rows harmless

    float dts;
    {
        int r = ridx[iS];
        float t0 = ts[iS], t1 = te[iS];
        float tmid = (t0 + t1) * 0.5f;

        float ox = ro[3 * r + 0], oy = ro[3 * r + 1], oz = ro[3 * r + 2];
        float dx = rd[3 * r + 0], dy = rd[3 * r + 1], dz = rd[3 * r + 2];

        float a0 = aabb[0], a1 = aabb[1], a2 = aabb[2];
        float a3 = aabb[3], a4 = aabb[4], a5 = aabb[5];

        float xn0 = (ox + dx * tmid - a0) / (a3 - a0 + 1e-5f);
        float xn1 = (oy + dy * tmid - a1) / (a4 - a1 + 1e-5f);
        float xn2 = (oz + dz * tmid - a2) / (a5 - a2 + 1e-5f);

        bool sel = (xn0 > 0.f) && (xn0 < 1.f) &&
                   (xn1 > 0.f) && (xn1 < 1.f) &&
                   (xn2 > 0.f) && (xn2 < 1.f);
        dts = sel ? (t1 - t0) : 0.f;

        float xc0 = fminf(fmaxf(xn0, 0.f), 1.f);
        float xc1 = fminf(fmaxf(xn1, 0.f), 1.f);
        float xc2 = fminf(fmaxf(xn2, 0.f), 1.f);

        const float2* __restrict__ tb = (const float2*)tables;
        unsigned* erow = wp + WP_A + lane * 17;

#pragma unroll
        for (int l = 0; l < 16; l++) {
            float rs = res.r[l];
            float px = xc0 * rs, py = xc1 * rs, pz = xc2 * rs;
            float p0x = floorf(px), p0y = floorf(py), p0z = floorf(pz);
            float fx = px - p0x, fy = py - p0y, fz = pz - p0z;
            unsigned ux = (unsigned)p0x, uy = (unsigned)p0y, uz = (unsigned)p0z;
            unsigned hx0 = ux,               hx1 = ux + 1u;
            unsigned hy0 = uy * 2654435761u, hy1 = (uy + 1u) * 2654435761u;
            unsigned hz0 = uz * 805459861u,  hz1 = (uz + 1u) * 805459861u;
            float wx0 = 1.f - fx, wy0 = 1.f - fy, wz0 = 1.f - fz;
            const float2* __restrict__ tp = tb + (size_t)l * TBL;
            float f0 = 0.f, f1 = 0.f;
#pragma unroll
            for (int cc = 0; cc < 8; cc++) {
                unsigned h = ((cc & 4) ? hx1 : hx0) ^ ((cc & 2) ? hy1 : hy0) ^ ((cc & 1) ? hz1 : hz0);
                h &= TMASK;
                float wgt = ((cc & 4) ? fx : wx0) * ((cc & 2) ? fy : wy0) * ((cc & 1) ? fz : wz0);
                float2 v = __ldg(tp + h);
                f0 = fmaf(v.x, wgt, f0);
                f1 = fmaf(v.y, wgt, f1);
            }
            erow[l] = packbf(f0, f1);
        }
        wpi[WP_RID + lane] = r;
    }
    __syncwarp();

    // ---------------- stages 1-2: X1 (regs) ; H2 -> smem f32 ----------------
    {
        unsigned encf[2][4][4];
        load_afrag<2, 17>(wp + WP_A, lane, encf);
        unsigned x1f[2][4][4];
        gemm<2, 64, false, true, false, 0, 0>(
            encf, nullptr, g_Wv0, nullptr, nullptr, nullptr, lane,
            x1f, nullptr, nullptr);
        gemm<4, 16, false, false, false, 2, 17>(
            x1f, nullptr, g_Wv1, nullptr, nullptr, nullptr, lane,
            nullptr, nullptr, wpf + WP_C);
    }
    __syncwarp();

    // ---------------- stage 3: repack (sig in register) ---------------------
    float sig_h0;
    {
        const float* hrow = wpf + WP_C + lane * 17;
        sig_h0 = hrow[0];
        unsigned* erow = wp + WP_EMB + lane * 9;
#pragma unroll
        for (int kp = 0; kp < 8; kp++) {
            float v0 = hrow[1 + 2 * kp];
            float v1 = (kp < 7) ? hrow[2 + 2 * kp] : 0.f;
            erow[kp] = packbf(v0, v1);
        }
    }
    __syncwarp();

    // ---------------- stages 4-6: X2 -> X3 -> X4 (registers) ---------------
    {
        unsigned embf[2][4][4];
        load_afrag<1, 9>(wp + WP_EMB, lane, embf);

        unsigned x2h[2][4][4], x2l[2][4][4];
        gemm<1, 64, false, true, true, 1, 0>(
            embf, nullptr, g_Wve, nullptr, g_raypart, wpi + WP_RID, lane,
            x2h, x2l, nullptr);

        unsigned x3h[2][4][4], x3l[2][4][4];
        gemm<4, 64, true, true, false, 1, 0>(
            x2h, x2l, nullptr, g_Wvh1, nullptr, nullptr, lane,
            x3h, x3l, nullptr);

        gemm<4, 8, true, false, false, 2, 9>(
            x3h, x3l, nullptr, g_Wvh2, nullptr, nullptr, lane,
            nullptr, nullptr, wpf + WP_A);
    }
    __syncwarp();

    // ---------------- epilogue ----------------------------------------------
    {
        if (gi0 < N) {
            float s = expf(sig_h0 - 1.f) * dts;
            float c0 = wpf[WP_A + lane * 9 + 0];
            float c1 = wpf[WP_A + lane * 9 + 1];
            float c2 = wpf[WP_A + lane * 9 + 2];
            g_samp[gi0] = make_float4(1.f / (1.f + expf(-c0)),
                                      1.f / (1.f + expf(-c1)),
                                      1.f / (1.f + expf(-c2)), s);
        }
    }
}

// ---------------------------------------------------------------------------
// accumulation: warp per ray, bounds from g_raystart (no binary search)
// ---------------------------------------------------------------------------
__global__ __launch_bounds__(256)
void accum_kernel(const float* __restrict__ ts, const float* __restrict__ te,
                  float* __restrict__ out, int N, int R)
{
    const unsigned FULL = 0xFFFFFFFFu;
    int warp = (blockIdx.x * blockDim.x + threadIdx.x) >> 5;
    int lane = threadIdx.x & 31;
    if (warp >= R) return;
    int r = warp;

    int start = g_raystart[r];
    int end   = g_raystart[r + 1];

    float carry = 0.f;
    float cr = 0.f, cg = 0.f, cb = 0.f, cw = 0.f, cd = 0.f;

    for (int base = start; base < end; base += 32) {
        int i = base + lane;
        bool v = i < end;
        float4 q = v ? g_samp[i] : make_float4(0.f, 0.f, 0.f, 0.f);
        float si = q.w;
        float tm = v ? 0.5f * (ts[i] + te[i]) : 0.f;

        float incl = si;
#pragma unroll
        for (int off = 1; off < 32; off <<= 1) {
            float t = __shfl_up_sync(FULL, incl, off);
            if (lane >= off) incl += t;
        }
        float excl  = carry + (incl - si);
        float trans = expf(-excl);
        float alpha = 1.f - expf(-si);
        float wgt = trans * alpha;

        cr += wgt * q.x;
        cg += wgt * q.y;
        cb += wgt * q.z;
        cw += wgt;
        cd += wgt * tm;

        carry += __shfl_sync(FULL, incl, 31);
    }

#pragma unroll
    for (int off = 16; off >= 1; off >>= 1) {
        cr += __shfl_xor_sync(FULL, cr, off);
        cg += __shfl_xor_sync(FULL, cg, off);
        cb += __shfl_xor_sync(FULL, cb, off);
        cw += __shfl_xor_sync(FULL, cw, off);
        cd += __shfl_xor_sync(FULL, cd, off);
    }

    if (lane == 0) {
        out[3 * r + 0] = cr;
        out[3 * r + 1] = cg;
        out[3 * r + 2] = cb;
        out[3 * R + r] = cw;
        out[4 * R + r] = cd / fmaxf(cw, 1.1920929e-7f);
    }
}

// ---------------------------------------------------------------------------
extern "C" void kernel_launch(void* const* d_in, const int* in_sizes, int n_in,
                              void* d_out, int out_size)
{
    const float* ts     = (const float*)d_in[0];
    const float* te     = (const float*)d_in[1];
    const float* ro     = (const float*)d_in[2];
    const float* rd     = (const float*)d_in[3];
    const int*   ridx   = (const int*)  d_in[4];
    const float* tables = (const float*)d_in[5];
    const float* w0     = (const float*)d_in[6];
    const float* w1     = (const float*)d_in[7];
    const float* hw0    = (const float*)d_in[8];
    const float* hw1    = (const float*)d_in[9];
    const float* hw2    = (const float*)d_in[10];
    const float* aabb   = (const float*)d_in[11];
    float* out = (float*)d_out;

    int N = in_sizes[0];
    int R = in_sizes[2] / 3;

    ResTable res;
    double scale = exp((log(4096.0) - log(16.0)) / 15.0);
    double acc = 16.0;
    for (int l = 0; l < 16; l++) { res.r[l] = (float)floor(acc); acc *= scale; }

    cudaFuncSetAttribute(fused_kernel, cudaFuncAttributeMaxDynamicSharedMemorySize,
                         SMEM_U32 * 4);

    prep_kernel<<<4, 256>>>(w0, w1, hw0, hw1, hw2);
    raypart_kernel<<<(R * 64 + 255) / 256, 256>>>(rd, hw0, R);
    raybounds_kernel<<<(N + 255) / 256, 256>>>(ridx, N, R);
    fused_kernel<<<(N + 127) / 128, 128, SMEM_U32 * 4>>>(
        ts, te, ro, rd, ridx, tables, aabb, res, N);
    accum_kernel<<<(R * 32 + 255) / 256, 256>>>(ts, te, out, N, R);
}

// round 17
// speedup vs baseline: 1.5307x; 1.5307x over previous
#include <cuda_runtime.h>
#include <cuda_bf16.h>
#include <math.h>
#include <stdint.h>

#define NMAX   (1 << 19)
#define RMAX   8192
#define TBL    (1 << 19)
#define TMASK  (TBL - 1)

// ---------------- global scratch ----------------
__device__ float4   g_samp[NMAX];          // {r,g,b,s}
__device__ float    g_raypart[RMAX * 64];  // SH(dir) @ hw0[0:16,:]  (fp32 exact)

// vectorized weight layouts: entry index = (ni*KS + ks)*32 + lane
__device__ uint2 g_Wv0 [8 * 2 * 32];       // X1: K=32,N=64, nosplit
__device__ uint2 g_Wv1 [2 * 4 * 32];       // H2: K=64,N=16, nosplit
__device__ uint2 g_Wve [8 * 1 * 32];       // X2: K=16,N=64, nosplit
__device__ uint4 g_Wvh1[8 * 4 * 32];       // X3: K=64,N=64, split {bh0,bh1,bl0,bl1}
__device__ uint4 g_Wvh2[1 * 4 * 32];       // X4: K=64,N=8,  split

struct ResTable { float r[16]; };

__device__ __forceinline__ unsigned packbf(float lo, float hi) {
    unsigned r;
    asm("cvt.rn.bf16x2.f32 %0, %1, %2;" : "=r"(r) : "f"(hi), "f"(lo));
    return r;
}
__device__ __forceinline__ float bfround(float v) {
    return __bfloat162float(__float2bfloat16_rn(v));
}

// ---------------------------------------------------------------------------
// prep: build vectorized bf16 weight layouts (hi/lo split for head l1,l2)
// ---------------------------------------------------------------------------
__global__ void prep_kernel(const float* __restrict__ w0, const float* __restrict__ w1,
                            const float* __restrict__ hw0, const float* __restrict__ hw1,
                            const float* __restrict__ hw2)
{
    int i = blockIdx.x * 256 + threadIdx.x;   // 0..1023
    int lane = i & 31, c = lane & 3, g = lane >> 2;

    // X3: hw1 (64x64), split, 1024 entries
    {
        int ni = i >> 7, ks = (i >> 5) & 3;
        int n = ni * 8 + g;
        int kp0 = ks * 8 + c, kp1 = kp0 + 4;
        float v00 = hw1[(2 * kp0) * 64 + n],     v01 = hw1[(2 * kp0 + 1) * 64 + n];
        float v10 = hw1[(2 * kp1) * 64 + n],     v11 = hw1[(2 * kp1 + 1) * 64 + n];
        float h00 = bfround(v00), h01 = bfround(v01);
        float h10 = bfround(v10), h11 = bfround(v11);
        g_Wvh1[i] = make_uint4(packbf(h00, h01), packbf(h10, h11),
                               packbf(v00 - h00, v01 - h01), packbf(v10 - h10, v11 - h11));
    }
    // X1: w0 (32x64), nosplit, 512 entries
    if (i < 512) {
        int ni = i >> 6, ks = (i >> 5) & 1;
        int n = ni * 8 + g;
        int kp0 = ks * 8 + c, kp1 = kp0 + 4;
        g_Wv0[i] = make_uint2(packbf(w0[(2 * kp0) * 64 + n], w0[(2 * kp0 + 1) * 64 + n]),
                              packbf(w0[(2 * kp1) * 64 + n], w0[(2 * kp1 + 1) * 64 + n]));
    }
    // H2: w1 (64x16), nosplit, 256 entries
    if (i < 256) {
        int ni = i >> 7, ks = (i >> 5) & 3;
        int n = ni * 8 + g;
        int kp0 = ks * 8 + c, kp1 = kp0 + 4;
        g_Wv1[i] = make_uint2(packbf(w1[(2 * kp0) * 16 + n], w1[(2 * kp0 + 1) * 16 + n]),
                              packbf(w1[(2 * kp1) * 16 + n], w1[(2 * kp1 + 1) * 16 + n]));
    }
    // X2: hw0 emb rows 16..30 (k-logical 0..14, pad 15), nosplit, 256 entries
    if (i < 256) {
        int ni = i >> 5;
        int n = ni * 8 + g;
        int kp0 = c, kp1 = c + 4;
        float e00 = (2 * kp0     < 15) ? hw0[(16 + 2 * kp0)     * 64 + n] : 0.f;
        float e01 = (2 * kp0 + 1 < 15) ? hw0[(16 + 2 * kp0 + 1) * 64 + n] : 0.f;
        float e10 = (2 * kp1     < 15) ? hw0[(16 + 2 * kp1)     * 64 + n] : 0.f;
        float e11 = (2 * kp1 + 1 < 15) ? hw0[(16 + 2 * kp1 + 1) * 64 + n] : 0.f;
        g_Wve[i] = make_uint2(packbf(e00, e01), packbf(e10, e11));
    }
    // X4: hw2 (64x3 pad 8), split, 128 entries
    if (i < 128) {
        int ks = i >> 5;
        int kp0 = ks * 8 + c, kp1 = kp0 + 4;
        float v00 = (g < 3) ? hw2[(2 * kp0) * 3 + g]     : 0.f;
        float v01 = (g < 3) ? hw2[(2 * kp0 + 1) * 3 + g] : 0.f;
        float v10 = (g < 3) ? hw2[(2 * kp1) * 3 + g]     : 0.f;
        float v11 = (g < 3) ? hw2[(2 * kp1 + 1) * 3 + g] : 0.f;
        float h00 = bfround(v00), h01 = bfround(v01);
        float h10 = bfround(v10), h11 = bfround(v11);
        g_Wvh2[i] = make_uint4(packbf(h00, h01), packbf(h10, h11),
                               packbf(v00 - h00, v01 - h01), packbf(v10 - h10, v11 - h11));
    }
}

// ---------------------------------------------------------------------------
// per-ray SH @ hw0[0:16,:]  (fp32 exact)
// ---------------------------------------------------------------------------
__global__ void raypart_kernel(const float* __restrict__ rd,
                               const float* __restrict__ hw0, int R)
{
    int idx = blockIdx.x * 256 + threadIdx.x;
    if (idx >= R * 64) return;
    int r = idx >> 6, n = idx & 63;
    float x = rd[3 * r + 0], y = rd[3 * r + 1], z = rd[3 * r + 2];
    float x2 = x * x, y2 = y * y, z2 = z * z;
    float xy = x * y, yz = y * z, xz = x * z;
    float sh[16];
    sh[0]  = 0.28209479177387814f;
    sh[1]  = -0.48860251190291987f * y;
    sh[2]  =  0.48860251190291987f * z;
    sh[3]  = -0.48860251190291987f * x;
    sh[4]  =  1.0925484305920792f * xy;
    sh[5]  = -1.0925484305920792f * yz;
    sh[6]  =  0.94617469575756f * z2 - 0.31539156525252005f;
    sh[7]  = -1.0925484305920792f * xz;
    sh[8]  =  0.5462742152960396f * (x2 - y2);
    sh[9]  = -0.5900435899266435f * y * (3.f * x2 - y2);
    sh[10] =  2.890611442640554f * xy * z;
    sh[11] = -0.4570457994644658f * y * (4.f * z2 - x2 - y2);
    sh[12] =  0.3731763325901154f * z * (2.f * z2 - 3.f * x2 - 3.f * y2);
    sh[13] = -0.4570457994644658f * x * (4.f * z2 - x2 - y2);
    sh[14] =  1.445305721320277f * z * (x2 - y2);
    sh[15] = -0.5900435899266435f * x * (x2 - 3.f * y2);
    float acc = 0.f;
#pragma unroll
    for (int k = 0; k < 16; k++) acc = fmaf(sh[k], hw0[k * 64 + n], acc);
    g_raypart[r * 64 + n] = acc;
}

// ---------------------------------------------------------------------------
// mma + fragment helpers (identical numerics to R15)
// ---------------------------------------------------------------------------
__device__ __forceinline__ void mma16(float c[4], unsigned a0, unsigned a1,
                                      unsigned a2, unsigned a3,
                                      unsigned b0, unsigned b1)
{
    asm volatile(
        "mma.sync.aligned.m16n8k16.row.col.f32.bf16.bf16.f32 "
        "{%0,%1,%2,%3}, {%4,%5,%6,%7}, {%8,%9}, {%0,%1,%2,%3};"
        : "+f"(c[0]), "+f"(c[1]), "+f"(c[2]), "+f"(c[3])
        : "r"(a0), "r"(a1), "r"(a2), "r"(a3), "r"(b0), "r"(b1));
}

template <int KS, int SIN>
__device__ __forceinline__ void load_afrag(const unsigned* sIn, int lane,
                                           unsigned a[2][4][4])
{
    const int g = lane >> 2, c = lane & 3;
#pragma unroll
    for (int mi = 0; mi < 2; mi++) {
        const int rA = mi * 16 + g;
#pragma unroll
        for (int ks = 0; ks < KS; ks++) {
            a[mi][ks][0] = sIn[(rA    ) * SIN + ks * 8 + c];
            a[mi][ks][1] = sIn[(rA + 8) * SIN + ks * 8 + c];
            a[mi][ks][2] = sIn[(rA    ) * SIN + ks * 8 + c + 4];
            a[mi][ks][3] = sIn[(rA + 8) * SIN + ks * 8 + c + 4];
        }
    }
}

// OUTMODE: 0 = register frag (hi only), 1 = register frag hi+lo, 2 = smem f32
template <int KS_IN, int NOUT, bool SPLIT, bool RELU, bool RPINIT, int OUTMODE, int SOUT>
__device__ __forceinline__ void gemm(
    const unsigned aHi[2][4][4], const unsigned aLo[2][4][4],
    const uint2* __restrict__ Wv2, const uint4* __restrict__ Wv4,
    const float* __restrict__ rayPart, const int* sRid,
    int lane,
    unsigned oHi[2][4][4], unsigned oLo[2][4][4], float* outF)
{
    const int g = lane >> 2, c = lane & 3;
    int ridA[2], ridB[2];
    if (RPINIT) {
#pragma unroll
        for (int mi = 0; mi < 2; mi++) {
            ridA[mi] = sRid[mi * 16 + g];
            ridB[mi] = sRid[mi * 16 + g + 8];
        }
    }

#pragma unroll
    for (int ni = 0; ni < NOUT / 8; ni++) {
        float acc[2][4];
#pragma unroll
        for (int mi = 0; mi < 2; mi++) {
            if (RPINIT) {
                float2 pa = __ldg((const float2*)(rayPart + ridA[mi] * 64 + ni * 8 + 2 * c));
                float2 pb = __ldg((const float2*)(rayPart + ridB[mi] * 64 + ni * 8 + 2 * c));
                acc[mi][0] = pa.x; acc[mi][1] = pa.y; acc[mi][2] = pb.x; acc[mi][3] = pb.y;
            } else {
                acc[mi][0] = acc[mi][1] = acc[mi][2] = acc[mi][3] = 0.f;
            }
        }
#pragma unroll
        for (int ks = 0; ks < KS_IN; ks++) {
            if (SPLIT) {
                uint4 wv = __ldg(Wv4 + ((ni * KS_IN + ks) << 5) + lane);
#pragma unroll
                for (int mi = 0; mi < 2; mi++) {
                    mma16(acc[mi], aHi[mi][ks][0], aHi[mi][ks][1],
                                   aHi[mi][ks][2], aHi[mi][ks][3], wv.x, wv.y);
                    mma16(acc[mi], aLo[mi][ks][0], aLo[mi][ks][1],
                                   aLo[mi][ks][2], aLo[mi][ks][3], wv.x, wv.y);
                    mma16(acc[mi], aHi[mi][ks][0], aHi[mi][ks][1],
                                   aHi[mi][ks][2], aHi[mi][ks][3], wv.z, wv.w);
                }
            } else {
                uint2 wv = __ldg(Wv2 + ((ni * KS_IN + ks) << 5) + lane);
#pragma unroll
                for (int mi = 0; mi < 2; mi++) {
                    mma16(acc[mi], aHi[mi][ks][0], aHi[mi][ks][1],
                                   aHi[mi][ks][2], aHi[mi][ks][3], wv.x, wv.y);
                }
            }
        }
#pragma unroll
        for (int mi = 0; mi < 2; mi++) {
            const int rA = mi * 16 + g;
            float v0 = acc[mi][0], v1 = acc[mi][1], v2 = acc[mi][2], v3 = acc[mi][3];
            if (RELU) {
                v0 = fmaxf(v0, 0.f); v1 = fmaxf(v1, 0.f);
                v2 = fmaxf(v2, 0.f); v3 = fmaxf(v3, 0.f);
            }
            if (OUTMODE == 2) {
                outF[(rA    ) * SOUT + ni * 8 + 2 * c    ] = v0;
                outF[(rA    ) * SOUT + ni * 8 + 2 * c + 1] = v1;
                outF[(rA + 8) * SOUT + ni * 8 + 2 * c    ] = v2;
                outF[(rA + 8) * SOUT + ni * 8 + 2 * c + 1] = v3;
            } else {
                const int ks_o = ni >> 1, sl = (ni & 1) * 2;
                oHi[mi][ks_o][sl    ] = packbf(v0, v1);
                oHi[mi][ks_o][sl + 1] = packbf(v2, v3);
                if (OUTMODE == 1) {
                    float h0 = bfround(v0), h1 = bfround(v1);
                    float h2 = bfround(v2), h3 = bfround(v3);
                    oLo[mi][ks_o][sl    ] = packbf(v0 - h0, v1 - h1);
                    oLo[mi][ks_o][sl + 1] = packbf(v2 - h2, v3 - h3);
                }
            }
        }
    }
}

// ---------------------------------------------------------------------------
// FUSED kernel: hash encode (1 thread/sample, 16 levels) -> register-resident
// MLP chain. 128 samples / block, 4 independent warps (only __syncwarp).
// __launch_bounds__(128, 3): cap regs at 170 so 3 blocks (12 warps) fit per SM.
// per-warp slab (words):
//   WP_A   = 0     ENC s17 (544) / X4 f32 s9 (288, aliases; ENC dead after X1)
//   WP_C   = 544   H2 f32 s17 (544)
//   WP_EMB = 1088  s9 (288)
//   WP_RID = 1376  int x32
// ---------------------------------------------------------------------------
#define WP_A     0
#define WP_C     544
#define WP_EMB   1088
#define WP_RID   1376
#define WP_WORDS 1408
#define SMEM_U32 (4 * WP_WORDS)   // 5632 words = 22528 bytes

__global__ __launch_bounds__(128, 3)
void fused_kernel(
    const float* __restrict__ ts, const float* __restrict__ te,
    const float* __restrict__ ro, const float* __restrict__ rd,
    const int*   __restrict__ ridx,
    const float* __restrict__ tables,
    const float* __restrict__ aabb,
    ResTable res, int N)
{
    extern __shared__ unsigned smu[];

    const int lane = threadIdx.x & 31;
    const int w = threadIdx.x >> 5;
    unsigned* wp = smu + w * WP_WORDS;
    float*    wpf = (float*)wp;
    int*      wpi = (int*)wp;
    const int base = blockIdx.x * 128 + w * 32;

    // ---------------- stage 0: hash encode own sample -> smem enc row -------
    const int gi0 = base + lane;
    const int iS = (gi0 < N) ? gi0 : (N - 1);   // clamp; extra rows harmless

    float dts;
    {
        int r = ridx[iS];
        float t0 = ts[iS], t1 = te[iS];
        float tmid = (t0 + t1) * 0.5f;

        float ox = ro[3 * r + 0], oy = ro[3 * r + 1], oz = ro[3 * r + 2];
        float dx = rd[3 * r + 0], dy = rd[3 * r + 1], dz = rd[3 * r + 2];

        float a0 = aabb[0], a1 = aabb[1], a2 = aabb[2];
        float a3 = aabb[3], a4 = aabb[4], a5 = aabb[5];

        float xn0 = (ox + dx * tmid - a0) / (a3 - a0 + 1e-5f);
        float xn1 = (oy + dy * tmid - a1) / (a4 - a1 + 1e-5f);
        float xn2 = (oz + dz * tmid - a2) / (a5 - a2 + 1e-5f);

        bool sel = (xn0 > 0.f) && (xn0 < 1.f) &&
                   (xn1 > 0.f) && (xn1 < 1.f) &&
                   (xn2 > 0.f) && (xn2 < 1.f);
        dts = sel ? (t1 - t0) : 0.f;

        float xc0 = fminf(fmaxf(xn0, 0.f), 1.f);
        float xc1 = fminf(fmaxf(xn1, 0.f), 1.f);
        float xc2 = fminf(fmaxf(xn2, 0.f), 1.f);

        const float2* __restrict__ tb = (const float2*)tables;
        unsigned* erow = wp + WP_A + lane * 17;

#pragma unroll
        for (int l = 0; l < 16; l++) {
            float rs = res.r[l];
            float px = xc0 * rs, py = xc1 * rs, pz = xc2 * rs;
            float p0x = floorf(px), p0y = floorf(py), p0z = floorf(pz);
            float fx = px - p0x, fy = py - p0y, fz = pz - p0z;
            unsigned ux = (unsigned)p0x, uy = (unsigned)p0y, uz = (unsigned)p0z;
            unsigned hx0 = ux,               hx1 = ux + 1u;
            unsigned hy0 = uy * 2654435761u, hy1 = (uy + 1u) * 2654435761u;
            unsigned hz0 = uz * 805459861u,  hz1 = (uz + 1u) * 805459861u;
            float wx0 = 1.f - fx, wy0 = 1.f - fy, wz0 = 1.f - fz;
            const float2* __restrict__ tp = tb + (size_t)l * TBL;
            float f0 = 0.f, f1 = 0.f;
#pragma unroll
            for (int cc = 0; cc < 8; cc++) {
                unsigned h = ((cc & 4) ? hx1 : hx0) ^ ((cc & 2) ? hy1 : hy0) ^ ((cc & 1) ? hz1 : hz0);
                h &= TMASK;
                float wgt = ((cc & 4) ? fx : wx0) * ((cc & 2) ? fy : wy0) * ((cc & 1) ? fz : wz0);
                float2 v = __ldg(tp + h);
                f0 = fmaf(v.x, wgt, f0);
                f1 = fmaf(v.y, wgt, f1);
            }
            erow[l] = packbf(f0, f1);
        }
        wpi[WP_RID + lane] = r;
    }
    __syncwarp();

    // ---------------- stages 1-2: X1 (regs) ; H2 -> smem f32 ----------------
    {
        unsigned encf[2][4][4];
        load_afrag<2, 17>(wp + WP_A, lane, encf);
        unsigned x1f[2][4][4];
        gemm<2, 64, false, true, false, 0, 0>(
            encf, nullptr, g_Wv0, nullptr, nullptr, nullptr, lane,
            x1f, nullptr, nullptr);
        gemm<4, 16, false, false, false, 2, 17>(
            x1f, nullptr, g_Wv1, nullptr, nullptr, nullptr, lane,
            nullptr, nullptr, wpf + WP_C);
    }
    __syncwarp();

    // ---------------- stage 3: repack (sig in register) ---------------------
    float sig_h0;
    {
        const float* hrow = wpf + WP_C + lane * 17;
        sig_h0 = hrow[0];
        unsigned* erow = wp + WP_EMB + lane * 9;
#pragma unroll
        for (int kp = 0; kp < 8; kp++) {
            float v0 = hrow[1 + 2 * kp];
            float v1 = (kp < 7) ? hrow[2 + 2 * kp] : 0.f;
            erow[kp] = packbf(v0, v1);
        }
    }
    __syncwarp();

    // ---------------- stages 4-6: X2 -> X3 -> X4 (registers) ---------------
    {
        unsigned embf[2][4][4];
        load_afrag<1, 9>(wp + WP_EMB, lane, embf);

        unsigned x2h[2][4][4], x2l[2][4][4];
        gemm<1, 64, false, true, true, 1, 0>(
            embf, nullptr, g_Wve, nullptr, g_raypart, wpi + WP_RID, lane,
            x2h, x2l, nullptr);

        unsigned x3h[2][4][4], x3l[2][4][4];
        gemm<4, 64, true, true, false, 1, 0>(
            x2h, x2l, nullptr, g_Wvh1, nullptr, nullptr, lane,
            x3h, x3l, nullptr);

        gemm<4, 8, true, false, false, 2, 9>(
            x3h, x3l, nullptr, g_Wvh2, nullptr, nullptr, lane,
            nullptr, nullptr, wpf + WP_A);
    }
    __syncwarp();

    // ---------------- epilogue ----------------------------------------------
    {
        if (gi0 < N) {
            float s = expf(sig_h0 - 1.f) * dts;
            float c0 = wpf[WP_A + lane * 9 + 0];
            float c1 = wpf[WP_A + lane * 9 + 1];
            float c2 = wpf[WP_A + lane * 9 + 2];
            g_samp[gi0] = make_float4(1.f / (1.f + expf(-c0)),
                                      1.f / (1.f + expf(-c1)),
                                      1.f / (1.f + expf(-c2)), s);
        }
    }
}

// ---------------------------------------------------------------------------
// accumulation: warp per ray (R15 proven version — binary search bounds)
// ---------------------------------------------------------------------------
__global__ __launch_bounds__(256)
void accum_kernel(const float* __restrict__ ts, const float* __restrict__ te,
                  const int* __restrict__ ridx, float* __restrict__ out,
                  int N, int R)
{
    const unsigned FULL = 0xFFFFFFFFu;
    int warp = (blockIdx.x * blockDim.x + threadIdx.x) >> 5;
    int lane = threadIdx.x & 31;
    if (warp >= R) return;
    int r = warp;

    int lo = 0, hi = N;
    while (lo < hi) { int m = (lo + hi) >> 1; if (ridx[m] < r) lo = m + 1; else hi = m; }
    int start = lo;
    hi = N;
    while (lo < hi) { int m = (lo + hi) >> 1; if (ridx[m] < r + 1) lo = m + 1; else hi = m; }
    int end = lo;

    float carry = 0.f;
    float cr = 0.f, cg = 0.f, cb = 0.f, cw = 0.f, cd = 0.f;

    for (int base = start; base < end; base += 32) {
        int i = base + lane;
        bool v = i < end;
        float4 q = v ? g_samp[i] : make_float4(0.f, 0.f, 0.f, 0.f);
        float si = q.w;
        float tm = v ? 0.5f * (ts[i] + te[i]) : 0.f;

        float incl = si;
#pragma unroll
        for (int off = 1; off < 32; off <<= 1) {
            float t = __shfl_up_sync(FULL, incl, off);
            if (lane >= off) incl += t;
        }
        float excl  = carry + (incl - si);
        float trans = expf(-excl);
        float alpha = 1.f - expf(-si);
        float wgt = trans * alpha;

        cr += wgt * q.x;
        cg += wgt * q.y;
        cb += wgt * q.z;
        cw += wgt;
        cd += wgt * tm;

        carry += __shfl_sync(FULL, incl, 31);
    }

#pragma unroll
    for (int off = 16; off >= 1; off >>= 1) {
        cr += __shfl_xor_sync(FULL, cr, off);
        cg += __shfl_xor_sync(FULL, cg, off);
        cb += __shfl_xor_sync(FULL, cb, off);
        cw += __shfl_xor_sync(FULL, cw, off);
        cd += __shfl_xor_sync(FULL, cd, off);
    }

    if (lane == 0) {
        out[3 * r + 0] = cr;
        out[3 * r + 1] = cg;
        out[3 * r + 2] = cb;
        out[3 * R + r] = cw;
        out[4 * R + r] = cd / fmaxf(cw, 1.1920929e-7f);
    }
}

// ---------------------------------------------------------------------------
extern "C" void kernel_launch(void* const* d_in, const int* in_sizes, int n_in,
                              void* d_out, int out_size)
{
    const float* ts     = (const float*)d_in[0];
    const float* te     = (const float*)d_in[1];
    const float* ro     = (const float*)d_in[2];
    const float* rd     = (const float*)d_in[3];
    const int*   ridx   = (const int*)  d_in[4];
    const float* tables = (const float*)d_in[5];
    const float* w0     = (const float*)d_in[6];
    const float* w1     = (const float*)d_in[7];
    const float* hw0    = (const float*)d_in[8];
    const float* hw1    = (const float*)d_in[9];
    const float* hw2    = (const float*)d_in[10];
    const float* aabb   = (const float*)d_in[11];
    float* out = (float*)d_out;

    int N = in_sizes[0];
    int R = in_sizes[2] / 3;

    ResTable res;
    double scale = exp((log(4096.0) - log(16.0)) / 15.0);
    double acc = 16.0;
    for (int l = 0; l < 16; l++) { res.r[l] = (float)floor(acc); acc *= scale; }

    cudaFuncSetAttribute(fused_kernel, cudaFuncAttributeMaxDynamicSharedMemorySize,
                         SMEM_U32 * 4);

    prep_kernel<<<4, 256>>>(w0, w1, hw0, hw1, hw2);
    raypart_kernel<<<(R * 64 + 255) / 256, 256>>>(rd, hw0, R);
    fused_kernel<<<(N + 127) / 128, 128, SMEM_U32 * 4>>>(
        ts, te, ro, rd, ridx, tables, aabb, res, N);
    accum_kernel<<<(R * 32 + 255) / 256, 256>>>(ts, te, ridx, out, N, R);
}